// round 1
// baseline (speedup 1.0000x reference)
#include <cuda_runtime.h>
#include <cstdint>
#include <cmath>

// 134 MB scratch for the mid tensor x [4,128,256,256]
static __device__ float g_xmid[(size_t)4 * 128 * 256 * 256];

// ---------------------------------------------------------------------------
// 8-point complex FFT, decimation-in-time. s = +1: forward (e^{-i}), s = -1:
// inverse (e^{+i}), NO scaling. Fully unrolled, register-resident.
// ---------------------------------------------------------------------------
__device__ __forceinline__ void cfft8(float zr[8], float zi[8], const float s)
{
    const float cc = 0.70710678118654752440f;
    // even half: z0,z2,z4,z6
    float t0r = zr[0] + zr[4], t0i = zi[0] + zi[4];
    float t1r = zr[0] - zr[4], t1i = zi[0] - zi[4];
    float t2r = zr[2] + zr[6], t2i = zi[2] + zi[6];
    float t3r = zr[2] - zr[6], t3i = zi[2] - zi[6];
    float E0r = t0r + t2r, E0i = t0i + t2i;
    float E2r = t0r - t2r, E2i = t0i - t2i;
    float E1r = t1r + s * t3i, E1i = t1i - s * t3r;
    float E3r = t1r - s * t3i, E3i = t1i + s * t3r;
    // odd half: z1,z3,z5,z7
    float u0r = zr[1] + zr[5], u0i = zi[1] + zi[5];
    float u1r = zr[1] - zr[5], u1i = zi[1] - zi[5];
    float u2r = zr[3] + zr[7], u2i = zi[3] + zi[7];
    float u3r = zr[3] - zr[7], u3i = zi[3] - zi[7];
    float O0r = u0r + u2r, O0i = u0i + u2i;
    float O2r = u0r - u2r, O2i = u0i - u2i;
    float O1r = u1r + s * u3i, O1i = u1i - s * u3r;
    float O3r = u1r - s * u3i, O3i = u1i + s * u3r;
    // twiddles W8^{sk}
    float T0r = O0r, T0i = O0i;
    float T1r = cc * (O1r + s * O1i), T1i = cc * (O1i - s * O1r);
    float T2r = s * O2i,              T2i = -s * O2r;
    float T3r = cc * (s * O3i - O3r), T3i = -cc * (O3i + s * O3r);
    zr[0] = E0r + T0r; zi[0] = E0i + T0i;
    zr[4] = E0r - T0r; zi[4] = E0i - T0i;
    zr[1] = E1r + T1r; zi[1] = E1i + T1i;
    zr[5] = E1r - T1r; zi[5] = E1i - T1i;
    zr[2] = E2r + T2r; zi[2] = E2i + T2i;
    zr[6] = E2r - T2r; zi[6] = E2i - T2i;
    zr[3] = E3r + T3r; zi[3] = E3i + T3i;
    zr[7] = E3r - T3r; zi[7] = E3i - T3i;
}

// rfft2 of an 8x8 real patch (x[r*8+c], contiguous). Output: half spectrum
// F[u][v], u=0..7, v=0..4 stored at index u*5+v.
__device__ __forceinline__ void rfft2_8x8(const float* __restrict__ x,
                                          float Fr[40], float Fi[40])
{
    // rows: rfft along last axis (keep v = 0..4)
#pragma unroll
    for (int r = 0; r < 8; r++) {
        float zr[8], zi[8];
#pragma unroll
        for (int c = 0; c < 8; c++) { zr[c] = x[r * 8 + c]; zi[c] = 0.f; }
        cfft8(zr, zi, 1.0f);
#pragma unroll
        for (int v = 0; v < 5; v++) { Fr[r * 5 + v] = zr[v]; Fi[r * 5 + v] = zi[v]; }
    }
    // columns: full complex fft along axis -2
#pragma unroll
    for (int v = 0; v < 5; v++) {
        float zr[8], zi[8];
#pragma unroll
        for (int u = 0; u < 8; u++) { zr[u] = Fr[u * 5 + v]; zi[u] = Fi[u * 5 + v]; }
        cfft8(zr, zi, 1.0f);
#pragma unroll
        for (int u = 0; u < 8; u++) { Fr[u * 5 + v] = zr[u]; Fi[u * 5 + v] = zi[u]; }
    }
}

// ---------------------------------------------------------------------------
// Kernel F: per patch (b, ph, pw): 1x1 convs (GEMM 256x64, k=64) + forward
// FFTs + filter + combine + inverse FFT; writes un-patched x to g_xmid.
// smem (floats):
//   [0,16384)      sWT  [64][256]  weights transposed (img | event)
//   [16384,24576)  sIn  [2][64][64] pixels
//   [24576,41216)  sMid [256][65]  GEMM results (padded rows)
//   [41216,46464)  sFilt[128][41]
//   sFFT [256][81] aliases [0,20736) after the GEMM phase.
// ---------------------------------------------------------------------------
__global__ void __launch_bounds__(256) kF(const float* __restrict__ img,
                                          const float* __restrict__ evt,
                                          const float* __restrict__ w_img,
                                          const float* __restrict__ w_evt,
                                          const float* __restrict__ filt)
{
    extern __shared__ float sm[];
    float* sWT   = sm;            // [64][256]
    float* sIn   = sm + 16384;    // [2][64][64]
    float* sMid  = sm + 24576;    // [256][65]
    float* sFilt = sm + 41216;    // [128][41]
    float* sFFT  = sm;            // [256][81], reuses sWT+sIn region

    const int tid = threadIdx.x;
    const int pw = blockIdx.x, ph = blockIdx.y, b = blockIdx.z;

    // load weights transposed: sWT[k][o] (o<128: img, o>=128: event)
    for (int i = tid; i < 64 * 128; i += 256) {
        int k = i >> 7, o = i & 127;
        sWT[k * 256 + o]       = w_img[o * 64 + k];
        sWT[k * 256 + 128 + o] = w_evt[o * 64 + k];
    }
    // filter [128][40] -> padded [128][41]
    for (int i = tid; i < 128 * 40; i += 256) {
        int o = i / 40, j = i - o * 40;
        sFilt[o * 41 + j] = filt[i];
    }
    // patch pixels: 64 channels x 64 px, float4 loads
    {
        const float4* img4 = reinterpret_cast<const float4*>(img);
        const float4* evt4 = reinterpret_cast<const float4*>(evt);
        for (int i = tid; i < 64 * 16; i += 256) {
            int c = i >> 4, q = i & 15;
            int r = q >> 1, h = q & 1;
            int g4 = (((b * 64 + c) * 256 + ph * 8 + r) * 256 + pw * 8) / 4 + h;
            float4 v0 = img4[g4];
            float4 v1 = evt4[g4];
            *reinterpret_cast<float4*>(&sIn[c * 64 + q * 4])        = v0;
            *reinterpret_cast<float4*>(&sIn[4096 + c * 64 + q * 4]) = v1;
        }
    }
    __syncthreads();

    // GEMM: rows 0..255 (channel slots) x cols 0..63 (pixels), k = 64
    {
        int rb = tid >> 3, cb = tid & 7;
        int r0 = rb * 8, c0 = cb * 8;
        const float* pin = sIn + ((r0 >= 128) ? 4096 : 0);
        float acc[64];
#pragma unroll
        for (int i = 0; i < 64; i++) acc[i] = 0.f;
#pragma unroll 4
        for (int k = 0; k < 64; k++) {
            float4 w0 = *reinterpret_cast<const float4*>(&sWT[k * 256 + r0]);
            float4 w1 = *reinterpret_cast<const float4*>(&sWT[k * 256 + r0 + 4]);
            float4 x0 = *reinterpret_cast<const float4*>(&pin[k * 64 + c0]);
            float4 x1 = *reinterpret_cast<const float4*>(&pin[k * 64 + c0 + 4]);
            float wv[8] = {w0.x, w0.y, w0.z, w0.w, w1.x, w1.y, w1.z, w1.w};
            float xv[8] = {x0.x, x0.y, x0.z, x0.w, x1.x, x1.y, x1.z, x1.w};
#pragma unroll
            for (int i = 0; i < 8; i++)
#pragma unroll
                for (int j = 0; j < 8; j++)
                    acc[i * 8 + j] = fmaf(wv[i], xv[j], acc[i * 8 + j]);
        }
#pragma unroll
        for (int i = 0; i < 8; i++)
#pragma unroll
            for (int j = 0; j < 8; j++)
                sMid[(r0 + i) * 65 + c0 + j] = acc[i * 8 + j];
    }
    __syncthreads();   // after this, sWT/sIn region is reusable as sFFT

    // forward FFTs: threads 0..127 -> event (with filter), 128..255 -> img
    {
        int o = tid & 127;
        bool isEvt = (tid < 128);
        const float* src = sMid + (isEvt ? (128 + o) : o) * 65;
        float Fr[40], Fi[40];
        rfft2_8x8(src, Fr, Fi);
        if (isEvt) {
#pragma unroll
            for (int j = 0; j < 40; j++) {
                float f = sFilt[o * 41 + j];
                Fr[j] *= f; Fi[j] *= f;
            }
        }
        float* dst = sFFT + (isEvt ? o : (128 + o)) * 81;
#pragma unroll
        for (int j = 0; j < 40; j++) { dst[j] = Fr[j]; dst[40 + j] = Fi[j]; }
    }
    __syncthreads();

    // combine + inverse (threads 0..127, one channel each)
    if (tid < 128) {
        int o = tid;
        const float* ev = sFFT + o * 81;
        const float* im = sFFT + (128 + o) * 81;
        float Xr[40], Xi[40];
#pragma unroll
        for (int j = 0; j < 40; j++) {
            float er = ev[j], ei = ev[40 + j];
            float ir = im[j] + 1.0f, ii = im[40 + j];
            Xr[j] = ir * er - ii * ei;
            Xi[j] = ir * ei + ii * er;
        }
        // inverse fft along columns (axis -2)
#pragma unroll
        for (int v = 0; v < 5; v++) {
            float zr[8], zi[8];
#pragma unroll
            for (int u = 0; u < 8; u++) { zr[u] = Xr[u * 5 + v]; zi[u] = Xi[u * 5 + v]; }
            cfft8(zr, zi, -1.0f);
#pragma unroll
            for (int u = 0; u < 8; u++) { Xr[u * 5 + v] = zr[u]; Xi[u * 5 + v] = zi[u]; }
        }
        // irfft along rows (hermitian extension; real part only), scale 1/64
        float* outp = g_xmid + (((size_t)(b * 128 + o) * 256 + ph * 8) * 256 + pw * 8);
        const float sc = 1.0f / 64.0f;
#pragma unroll
        for (int r = 0; r < 8; r++) {
            float zr[8], zi[8];
#pragma unroll
            for (int v = 0; v < 5; v++) { zr[v] = Xr[r * 5 + v]; zi[v] = Xi[r * 5 + v]; }
            zr[5] = Xr[r * 5 + 3]; zi[5] = -Xi[r * 5 + 3];
            zr[6] = Xr[r * 5 + 2]; zi[6] = -Xi[r * 5 + 2];
            zr[7] = Xr[r * 5 + 1]; zi[7] = -Xi[r * 5 + 1];
            cfft8(zr, zi, -1.0f);
            float4 o0 = {zr[0] * sc, zr[1] * sc, zr[2] * sc, zr[3] * sc};
            float4 o1 = {zr[4] * sc, zr[5] * sc, zr[6] * sc, zr[7] * sc};
            *reinterpret_cast<float4*>(&outp[r * 256])     = o0;
            *reinterpret_cast<float4*>(&outp[r * 256 + 4]) = o1;
        }
    }
}

// ---------------------------------------------------------------------------
// Kernel D: 16x16 output tile per block. Depthwise 3x3 (SAME, zero pad) on
// channels c and c+64, exact GELU gate, then 64x64 out 1x1 GEMM.
// smem (floats): sG[64][256]=16384 | sWoT[64][64]=4096 | sWdw[1152] | sHalo[2][18][20]=720
// ---------------------------------------------------------------------------
__global__ void __launch_bounds__(256) kD(const float* __restrict__ w_dw,
                                          const float* __restrict__ w_out,
                                          float* __restrict__ out)
{
    extern __shared__ float sm[];
    float* sG    = sm;           // [64][256]
    float* sWoT  = sm + 16384;   // [64][64] transposed: sWoT[k][o]
    float* sWdw  = sm + 20480;   // [128][9]
    float* sHalo = sm + 21632;   // [2][18][20]

    const int tid = threadIdx.x;
    const int bx = blockIdx.x, by = blockIdx.y, b = blockIdx.z;
    const int x0 = bx * 16, y0 = by * 16;

    for (int i = tid; i < 64 * 64; i += 256) {
        int k = i >> 6, o = i & 63;
        sWoT[k * 64 + o] = w_out[o * 64 + k];
    }
    for (int i = tid; i < 128 * 9; i += 256) sWdw[i] = w_dw[i];

    const int py = tid >> 4, px = tid & 15;
    const size_t cbase = (size_t)b * 128 * 65536;

    for (int c = 0; c < 64; c++) {
        __syncthreads();  // protect sHalo reuse (also covers sWdw on iter 0)
        for (int i = tid; i < 324; i += 256) {
            int y = i / 18, x = i - y * 18;
            int gy = y0 + y - 1, gx = x0 + x - 1;
            float v0 = 0.f, v1 = 0.f;
            if (gy >= 0 && gy < 256 && gx >= 0 && gx < 256) {
                size_t gi = cbase + (size_t)c * 65536 + (size_t)gy * 256 + gx;
                v0 = g_xmid[gi];
                v1 = g_xmid[gi + (size_t)64 * 65536];
            }
            sHalo[y * 20 + x]       = v0;
            sHalo[360 + y * 20 + x] = v1;
        }
        __syncthreads();
        float a = 0.f, bb = 0.f;
#pragma unroll
        for (int dy = 0; dy < 3; dy++)
#pragma unroll
            for (int dx = 0; dx < 3; dx++) {
                float w1 = sWdw[c * 9 + dy * 3 + dx];
                float w2 = sWdw[(c + 64) * 9 + dy * 3 + dx];
                a  = fmaf(sHalo[(py + dy) * 20 + px + dx],       w1, a);
                bb = fmaf(sHalo[360 + (py + dy) * 20 + px + dx], w2, bb);
            }
        float gl = 0.5f * a * (1.0f + erff(a * 0.70710678118654752f));
        sG[c * 256 + tid] = gl * bb;
    }
    __syncthreads();

    // out GEMM: 64 oc x 256 px, k = 64; per thread 8 oc x 8 px
    int ob = tid >> 5, pb = tid & 31;
    int oc0 = ob * 8, p0 = pb * 8;
    float acc[64];
#pragma unroll
    for (int i = 0; i < 64; i++) acc[i] = 0.f;
#pragma unroll 4
    for (int k = 0; k < 64; k++) {
        float4 w0 = *reinterpret_cast<const float4*>(&sWoT[k * 64 + oc0]);
        float4 w1 = *reinterpret_cast<const float4*>(&sWoT[k * 64 + oc0 + 4]);
        float4 g0 = *reinterpret_cast<const float4*>(&sG[k * 256 + p0]);
        float4 g1 = *reinterpret_cast<const float4*>(&sG[k * 256 + p0 + 4]);
        float wv[8] = {w0.x, w0.y, w0.z, w0.w, w1.x, w1.y, w1.z, w1.w};
        float gv[8] = {g0.x, g0.y, g0.z, g0.w, g1.x, g1.y, g1.z, g1.w};
#pragma unroll
        for (int i = 0; i < 8; i++)
#pragma unroll
            for (int j = 0; j < 8; j++)
                acc[i * 8 + j] = fmaf(wv[i], gv[j], acc[i * 8 + j]);
    }
    // write: each 8-px group is a half row of the 16x16 tile
    int wy = y0 + (p0 >> 4);
    int wx = x0 + (p0 & 15);
#pragma unroll
    for (int i = 0; i < 8; i++) {
        size_t ga = ((size_t)(b * 64 + oc0 + i) * 256 + wy) * 256 + wx;
        float4 q0 = {acc[i * 8 + 0], acc[i * 8 + 1], acc[i * 8 + 2], acc[i * 8 + 3]};
        float4 q1 = {acc[i * 8 + 4], acc[i * 8 + 5], acc[i * 8 + 6], acc[i * 8 + 7]};
        *reinterpret_cast<float4*>(&out[ga])     = q0;
        *reinterpret_cast<float4*>(&out[ga + 4]) = q1;
    }
}

// ---------------------------------------------------------------------------
extern "C" void kernel_launch(void* const* d_in, const int* in_sizes, int n_in,
                              void* d_out, int out_size)
{
    const float* img   = (const float*)d_in[0];
    const float* evt   = (const float*)d_in[1];
    const float* w_img = (const float*)d_in[2];
    const float* w_evt = (const float*)d_in[3];
    const float* w_dw  = (const float*)d_in[4];
    const float* filt  = (const float*)d_in[5];
    const float* w_out = (const float*)d_in[6];
    float* out = (float*)d_out;

    const int smemF = 46464 * 4;  // 185,856 B
    const int smemD = 22352 * 4;  //  89,408 B
    cudaFuncSetAttribute(kF, cudaFuncAttributeMaxDynamicSharedMemorySize, smemF);
    cudaFuncSetAttribute(kD, cudaFuncAttributeMaxDynamicSharedMemorySize, smemD);

    kF<<<dim3(32, 32, 4), 256, smemF>>>(img, evt, w_img, w_evt, filt);
    kD<<<dim3(16, 16, 4), 256, smemD>>>(w_dw, w_out, out);
}